// round 14
// baseline (speedup 1.0000x reference)
#include <cuda_runtime.h>
#include <cuda_fp16.h>

// TensorialCP encoder: out[n, c] = Sx[c](x_n) * Sy[c](y_n) * Sz[c](z_n)
// 1-D bilinear sampling of three [32, 512] tables, align_corners=True.
//
// R11 (resubmit): two points per thread (warp = 8 points/iter) for 2x
// memory-level parallelism; 768 threads/CTA so the register budget (~85)
// fits the wider pipeline without spills (1024 thr caps at 64 regs ->
// local spills through L1, the bottleneck pipe).
//
// Table: per row (128B) 8 groups of [lo0..3 | d0..3] halves (d = g[r+1]-g[r]);
// one conflict-free LDS.128 per axis per point gives 4 components in
// HFMA2-ready form. Products + output stay fp32.

#define NCOMP 32
#define RES   512
#define HALVES_PER_ROW  64
#define HALVES_PER_AXIS (RES * HALVES_PER_ROW)    // 32768
#define HALVES_TOTAL    (3 * HALVES_PER_AXIS)     // 98304 halves = 192 KB
#define SMEM_BYTES      (HALVES_TOTAL * 2)        // 196608 B
#define THREADS 768

__device__ __half g_tab[HALVES_TOTAL];

// ---------------- prep: build (lo, d) half table -----------------------
__global__ void cp_prep_kernel(const float* __restrict__ vx,
                               const float* __restrict__ vy,
                               const float* __restrict__ vz) {
    int i = blockIdx.x * blockDim.x + threadIdx.x;
    if (i >= 3 * RES * NCOMP) return;
    int a   = i >> 14;
    int rem = i & 16383;
    int r   = rem >> 5;
    int c   = rem & 31;
    const float* src = (a == 0) ? vx : ((a == 1) ? vy : vz);
    float lo = src[(c << 9) + r];
    float hi = (r < RES - 1) ? src[(c << 9) + r + 1] : lo;  // d=0 at r=511
    int base = a * HALVES_PER_AXIS + (r << 6) + ((c >> 2) << 3) + (c & 3);
    g_tab[base]     = __float2half_rn(lo);
    g_tab[base + 4] = __float2half_rn(hi - lo);
}

// ---------------- main kernel ------------------------------------------

__device__ __forceinline__ uint4 row_load(const __half* __restrict__ base,
                                          float coord, float& w) {
    float ix = fmaf(coord, 255.5f, 255.5f);     // [-1,1] -> [0,511]
    float fi = floorf(ix);
    w = ix - fi;
    int i0 = (int)fi;                           // in [0,511] by construction
    return *(const uint4*)(base + (i0 << 6));
}

__device__ __forceinline__ float4 lerp4(uint4 u, float w) {
    const __half2* h = (const __half2*)&u;      // lo01 lo23 d01 d23
    __half2 w2 = __float2half2_rn(w);
    __half2 r01 = __hfma2(w2, h[2], h[0]);
    __half2 r23 = __hfma2(w2, h[3], h[1]);
    float2 a = __half22float2(r01);
    float2 b = __half22float2(r23);
    return make_float4(a.x, a.y, b.x, b.y);
}

__global__ __launch_bounds__(THREADS, 1)
void cp_encoder_kernel(const float* __restrict__ pos,
                       float* __restrict__ out,
                       int N, int totalWarps) {
    extern __shared__ __half tab[];

    int tid = threadIdx.x;

    // Linear, coalesced, conflict-free 192KB smem fill (L2-resident).
    {
        const float4* gp = (const float4*)g_tab;
        float4*       sp = (float4*)tab;
#pragma unroll
        for (int k = 0; k < 16; k++) {          // 16 * 768 = 12288 float4
            sp[tid + k * THREADS] = gp[tid + k * THREADS];
        }
    }
    __syncthreads();

    int lane = tid & 31;
    int sub  = lane >> 3;                 // which of the warp's 4 point-slots
    int cl   = lane & 7;                  // component group (4 comps)

    const __half* bx = tab + (cl << 3);   // by/bz folded as +32768/+65536

    int warpGlobal = blockIdx.x * (THREADS >> 5) + (tid >> 5);
    int stride     = totalWarps * 8;      // 8 points per warp per iter
    int p          = warpGlobal * 8 + sub;  // point A; point B = p + 4

    // one-iteration position prefetch for both points
    bool v0 = (p < N), v1 = (p + 4 < N);
    float xa = 0.f, ya = 0.f, za = 0.f, xb = 0.f, yb = 0.f, zb = 0.f;
    if (v0) {
        xa = __ldg(&pos[3 * p + 0]);
        ya = __ldg(&pos[3 * p + 1]);
        za = __ldg(&pos[3 * p + 2]);
    }
    if (v1) {
        xb = __ldg(&pos[3 * (p + 4) + 0]);
        yb = __ldg(&pos[3 * (p + 4) + 1]);
        zb = __ldg(&pos[3 * (p + 4) + 2]);
    }

    while (v0) {
        int  pn  = p + stride;
        bool nv0 = (pn < N), nv1 = (pn + 4 < N);
        float nxa = 0.f, nya = 0.f, nza = 0.f, nxb = 0.f, nyb = 0.f, nzb = 0.f;
        if (nv0) {
            nxa = __ldg(&pos[3 * pn + 0]);
            nya = __ldg(&pos[3 * pn + 1]);
            nza = __ldg(&pos[3 * pn + 2]);
        }
        if (nv1) {
            nxb = __ldg(&pos[3 * (pn + 4) + 0]);
            nyb = __ldg(&pos[3 * (pn + 4) + 1]);
            nzb = __ldg(&pos[3 * (pn + 4) + 2]);
        }

        // issue all 6 row loads back-to-back (independent -> 6 LDS in flight)
        float wxa, wya, wza, wxb, wyb, wzb;
        uint4 uxa = row_load(bx,                       xa, wxa);
        uint4 uya = row_load(bx + HALVES_PER_AXIS,     ya, wya);
        uint4 uza = row_load(bx + 2 * HALVES_PER_AXIS, za, wza);
        uint4 uxb = row_load(bx,                       xb, wxb);
        uint4 uyb = row_load(bx + HALVES_PER_AXIS,     yb, wyb);
        uint4 uzb = row_load(bx + 2 * HALVES_PER_AXIS, zb, wzb);

        float4 fxa = lerp4(uxa, wxa);
        float4 fya = lerp4(uya, wya);
        float4 fza = lerp4(uza, wza);
        float4 oa;
        oa.x = fxa.x * fya.x * fza.x;
        oa.y = fxa.y * fya.y * fza.y;
        oa.z = fxa.z * fya.z * fza.z;
        oa.w = fxa.w * fya.w * fza.w;
        __stcs((float4*)(out + ((size_t)p << 5) + (cl << 2)), oa);

        if (v1) {
            float4 fxb = lerp4(uxb, wxb);
            float4 fyb = lerp4(uyb, wyb);
            float4 fzb = lerp4(uzb, wzb);
            float4 ob;
            ob.x = fxb.x * fyb.x * fzb.x;
            ob.y = fxb.y * fyb.y * fzb.y;
            ob.z = fxb.z * fyb.z * fzb.z;
            ob.w = fxb.w * fyb.w * fzb.w;
            __stcs((float4*)(out + ((size_t)(p + 4) << 5) + (cl << 2)), ob);
        }

        p = pn; v0 = nv0; v1 = nv1;
        xa = nxa; ya = nya; za = nza;
        xb = nxb; yb = nyb; zb = nzb;
    }
}

extern "C" void kernel_launch(void* const* d_in, const int* in_sizes, int n_in,
                              void* d_out, int out_size) {
    const float* pos = (const float*)d_in[0];
    const float* vx  = (const float*)d_in[1];
    const float* vy  = (const float*)d_in[2];
    const float* vz  = (const float*)d_in[3];
    float* out = (float*)d_out;

    int N = in_sizes[0] / 3;

    int sms = 148;
    cudaDeviceGetAttribute(&sms, cudaDevAttrMultiProcessorCount, 0);

    cudaFuncSetAttribute(cp_encoder_kernel,
                         cudaFuncAttributeMaxDynamicSharedMemorySize,
                         SMEM_BYTES);

    cp_prep_kernel<<<(3 * RES * NCOMP + 255) / 256, 256>>>(vx, vy, vz);

    int totalWarps = sms * (THREADS / 32);
    cp_encoder_kernel<<<sms, THREADS, SMEM_BYTES>>>(pos, out, N, totalWarps);
}